// round 5
// baseline (speedup 1.0000x reference)
#include <cuda_runtime.h>
#include <math.h>

#define NB 2048
#define NT 64
#define ND 15
#define NH 256
#define TB 32        // batch rows per GRU CTA (sorted tile)
#define NBT 64       // NB / TB
#define THR 128
#define WHH_N (2 * 4 * 256 * 192)

typedef unsigned long long u64;

// ---------------- f32x2 packed-FMA helpers ----------------
__device__ __forceinline__ void ffma2(u64& d, u64 a, u64 b) {
  asm("fma.rn.f32x2 %0, %1, %2, %3;" : "=l"(d) : "l"(a), "l"(b), "l"(d));
}
__device__ __forceinline__ u64 splat2(float w) {
  u64 d; asm("mov.b64 %0, {%1, %1};" : "=l"(d) : "f"(w)); return d;
}
__device__ __forceinline__ u64 pack2(float lo, float hi) {
  u64 d; asm("mov.b64 %0, {%1, %2};" : "=l"(d) : "f"(lo), "f"(hi)); return d;
}
__device__ __forceinline__ float2 unpk2(u64 v) {
  float2 r; asm("mov.b64 {%0, %1}, %2;" : "=f"(r.x), "=f"(r.y) : "l"(v)); return r;
}

// ---------------- mbarrier / bulk-copy helpers ----------------
__device__ __forceinline__ unsigned smem_u32(const void* p) {
  unsigned a;
  asm("{ .reg .u64 t; cvta.to.shared.u64 t, %1; cvt.u32.u64 %0, t; }" : "=r"(a) : "l"(p));
  return a;
}
__device__ __forceinline__ void mbar_init(unsigned mbar, unsigned cnt) {
  asm volatile("mbarrier.init.shared.b64 [%0], %1;" :: "r"(mbar), "r"(cnt) : "memory");
}
__device__ __forceinline__ void mbar_expect(unsigned mbar, unsigned bytes) {
  asm volatile("mbarrier.arrive.expect_tx.shared.b64 _, [%0], %1;"
               :: "r"(mbar), "r"(bytes) : "memory");
}
__device__ __forceinline__ void bulk_g2s(unsigned dst, const void* src,
                                         unsigned bytes, unsigned mbar) {
  asm volatile(
      "cp.async.bulk.shared::cta.global.mbarrier::complete_tx::bytes [%0], [%1], %2, [%3];"
      :: "r"(dst), "l"(src), "r"(bytes), "r"(mbar) : "memory");
}
__device__ __forceinline__ void mbar_wait(unsigned mbar, unsigned parity) {
  asm volatile(
      "{\n\t.reg .pred P;\n\t"
      "W%=:\n\t"
      "mbarrier.try_wait.parity.acquire.cta.shared::cta.b64 P, [%0], %1, 0x989680;\n\t"
      "@P bra.uni D%=;\n\t"
      "bra.uni W%=;\n\t"
      "D%=:\n\t}"
      :: "r"(mbar), "r"(parity) : "memory");
}

// ---------------- device scratch ----------------
__device__ float g_h[2][2][NB][NH];          // [parity][gru][sorted_pos][h]
__device__ float g_whhB[WHH_N];              // [g][jt][k][gate*64+c]
__device__ float g_wblk[8][3136];            // [g*4+jt]{ wihT[15][192], cbA[192], cbHn[64] }
__device__ float g_xin[2][NB][272];
__device__ float g_a1[2][NB][1024];
__device__ float g_a2[2][NB][1024];
__device__ float g_a3[2][NB][512];
__device__ float g_a4[2][NB][256];
__device__ int   g_perm[NB];
__device__ int   g_off[66];
__device__ int   g_hist[66];
__device__ int   g_tilemax[NBT];
__device__ int   g_invpos[NB];
__device__ int   g_finparp[NB];
__device__ int   g_lsort[NB];

// ---------------- fused length sort (single block, 1024 threads) ----------------
__global__ void k_sort(const int* __restrict__ lengths) {
  int tid = threadIdx.x;
  if (tid < 66) g_hist[tid] = 0;
  __syncthreads();
  for (int b = tid; b < NB; b += 1024) atomicAdd(&g_hist[lengths[b]], 1);
  __syncthreads();
  if (tid == 0) {
    int s = 0;
    for (int l = 0; l < 66; ++l) { g_off[l] = s; s += g_hist[l]; }
  }
  __syncthreads();
  for (int b = tid; b < NB; b += 1024) {
    int p = atomicAdd(&g_off[lengths[b]], 1);
    g_perm[p] = b;
  }
  __syncthreads();
  if (tid < NBT) g_tilemax[tid] = lengths[g_perm[tid * TB + TB - 1]];
  __syncthreads();
  for (int p = tid; p < NB; p += 1024) {
    int b = g_perm[p];
    g_invpos[b] = p;
    g_finparp[p] = g_tilemax[p >> 5] & 1;
    g_lsort[p] = lengths[b];
  }
}

// ---------------- fused weight prep ----------------
__global__ void k_prep(const float* __restrict__ Whh0, const float* __restrict__ Whh1,
                       const float* __restrict__ Wih0, const float* __restrict__ bih0,
                       const float* __restrict__ bhh0,
                       const float* __restrict__ Wih1, const float* __restrict__ bih1,
                       const float* __restrict__ bhh1) {
  int i = blockIdx.x * blockDim.x + threadIdx.x;
  if (i < WHH_N) {
    int c  = i % 192;
    int k  = (i / 192) % 256;
    int jt = (i / (192 * 256)) & 3;
    int g  = i / (192 * 256 * 4);
    const float* W = g ? Whh1 : Whh0;
    int gg = c >> 6, cc = c & 63;
    g_whhB[i] = W[(size_t)(gg * 256 + jt * 64 + cc) * 256 + k];
    return;
  }
  int j = i - WHH_N;
  if (j >= 8 * 3136) return;
  int o  = j % 3136;
  int jt = (j / 3136) & 3;
  int g  = j / (3136 * 4);
  const float* Wih = g ? Wih1 : Wih0;
  const float* bih = g ? bih1 : bih0;
  const float* bhh = g ? bhh1 : bhh0;
  float v;
  if (o < 2880) {
    int k = o / 192, c = o % 192;
    int gg = c >> 6, cc = c & 63;
    v = Wih[(size_t)(gg * 256 + jt * 64 + cc) * ND + k];
  } else if (o < 3072) {
    int c = o - 2880;
    int gg = c >> 6, cc = c & 63;
    int row = gg * 256 + jt * 64 + cc;
    v = (gg < 2) ? (bih[row] + bhh[row]) : bih[row];
  } else {
    v = bhh[512 + jt * 64 + (o - 3072)];
  }
  g_wblk[g * 4 + jt][o] = v;
}

// ---------------- GRU step kernel ----------------
// 16 weight chunks of 16 k-rows (12288 B), 4 buffers, prefetch distance 3.
struct GruS {
  float hs[TB][256];       // 32768 B
  float wbuf[4][16][192];  // 49152 B
  float wih[15][192];      // 12544 B contiguous with cbA/cbHn
  float cbA[192];
  float cbHn[64];
  float xs[TB][ND];
  int   ls[TB];
  u64   mb[6];
};

#define ACC6(wA, wB, arr, hv0, hv1)                               \
  ffma2(arr[0][0][0], hv0, wA.x); ffma2(arr[0][0][1], hv0, wA.y); \
  ffma2(arr[0][1][0], hv0, wB.x); ffma2(arr[0][1][1], hv0, wB.y); \
  ffma2(arr[1][0][0], hv1, wA.x); ffma2(arr[1][0][1], hv1, wA.y); \
  ffma2(arr[1][1][0], hv1, wB.x); ffma2(arr[1][1][1], hv1, wB.y);

__global__ void __launch_bounds__(THR)
k_gru_step(const float* __restrict__ state, int t)
{
  extern __shared__ char sraw[];
  GruS& s = *reinterpret_cast<GruS*>(sraw);
  const int bt = blockIdx.x, jt = blockIdx.y, g = blockIdx.z;
  const int tid = threadIdx.x;
  const int pi = t & 1, po = pi ^ 1;

  if (t >= g_tilemax[bt]) return;   // frozen tile: nothing to do

  const unsigned mb_h = smem_u32(&s.mb[0]);
  unsigned mb_w[4];
  #pragma unroll
  for (int i = 0; i < 4; ++i) mb_w[i] = smem_u32(&s.mb[1 + i]);
  const int gjt = g * 4 + jt;
  const float* wsrc = g_whhB + (size_t)gjt * 256 * 192;

  if (tid == 0) {
    mbar_init(mb_h, 1);
    #pragma unroll
    for (int i = 0; i < 4; ++i) mbar_init(mb_w[i], 1);
  }
  __syncthreads();

  if (tid == 0) {
    if (t > 0) {
      mbar_expect(mb_h, 32768u + 12544u);
      bulk_g2s(smem_u32(&s.hs[0][0]), &g_h[pi][g][bt * TB][0], 32768u, mb_h);
      bulk_g2s(smem_u32(&s.wih[0][0]), &g_wblk[gjt][0], 12544u, mb_h);
      #pragma unroll
      for (int j = 0; j < 3; ++j) {
        mbar_expect(mb_w[j], 12288u);
        bulk_g2s(smem_u32(&s.wbuf[j][0][0]), wsrc + (size_t)j * 16 * 192, 12288u, mb_w[j]);
      }
    } else {
      mbar_expect(mb_h, 12544u);
      bulk_g2s(smem_u32(&s.wih[0][0]), &g_wblk[gjt][0], 12544u, mb_h);
    }
  }

  // x gather + lengths (overlaps TMA flight)
  for (int i = tid; i < TB * ND; i += THR) {
    int b = i / ND, c = i % ND;
    s.xs[b][c] = state[((size_t)g_perm[bt * TB + b] * NT + t) * ND + c];
  }
  if (tid < TB) s.ls[tid] = g_lsort[bt * TB + tid];
  __syncthreads();

  const int cg = tid & 7, bg = tid >> 3;
  const int b0 = bg * 2;
  const int qa = cg * 4, qb = 32 + cg * 4;

  u64 aR[2][2][2], aZ[2][2][2], aI[2][2][2], aN[2][2][2];

  mbar_wait(mb_h, 0);   // (h tile +) wih/biases landed

  {
    u64 rA0 = pack2(s.cbA[qa], s.cbA[qa+1]),          rA1 = pack2(s.cbA[qa+2], s.cbA[qa+3]);
    u64 rB0 = pack2(s.cbA[qb], s.cbA[qb+1]),          rB1 = pack2(s.cbA[qb+2], s.cbA[qb+3]);
    u64 zA0 = pack2(s.cbA[64+qa], s.cbA[64+qa+1]),    zA1 = pack2(s.cbA[64+qa+2], s.cbA[64+qa+3]);
    u64 zB0 = pack2(s.cbA[64+qb], s.cbA[64+qb+1]),    zB1 = pack2(s.cbA[64+qb+2], s.cbA[64+qb+3]);
    u64 iA0 = pack2(s.cbA[128+qa], s.cbA[128+qa+1]),  iA1 = pack2(s.cbA[128+qa+2], s.cbA[128+qa+3]);
    u64 iB0 = pack2(s.cbA[128+qb], s.cbA[128+qb+1]),  iB1 = pack2(s.cbA[128+qb+2], s.cbA[128+qb+3]);
    u64 nA0 = pack2(s.cbHn[qa], s.cbHn[qa+1]),        nA1 = pack2(s.cbHn[qa+2], s.cbHn[qa+3]);
    u64 nB0 = pack2(s.cbHn[qb], s.cbHn[qb+1]),        nB1 = pack2(s.cbHn[qb+2], s.cbHn[qb+3]);
    #pragma unroll
    for (int b = 0; b < 2; ++b) {
      aR[b][0][0] = rA0; aR[b][0][1] = rA1; aR[b][1][0] = rB0; aR[b][1][1] = rB1;
      aZ[b][0][0] = zA0; aZ[b][0][1] = zA1; aZ[b][1][0] = zB0; aZ[b][1][1] = zB1;
      aI[b][0][0] = iA0; aI[b][0][1] = iA1; aI[b][1][0] = iB0; aI[b][1][1] = iB1;
      aN[b][0][0] = nA0; aN[b][0][1] = nA1; aN[b][1][0] = nB0; aN[b][1][1] = nB1;
    }
  }

  // input-gate contribution (K = 15)
  #pragma unroll
  for (int k = 0; k < ND; ++k) {
    const float* wr = &s.wih[k][0];
    ulonglong2 rA = *reinterpret_cast<const ulonglong2*>(wr + qa);
    ulonglong2 rB = *reinterpret_cast<const ulonglong2*>(wr + qb);
    ulonglong2 zA = *reinterpret_cast<const ulonglong2*>(wr + 64 + qa);
    ulonglong2 zB = *reinterpret_cast<const ulonglong2*>(wr + 64 + qb);
    ulonglong2 nA = *reinterpret_cast<const ulonglong2*>(wr + 128 + qa);
    ulonglong2 nB = *reinterpret_cast<const ulonglong2*>(wr + 128 + qb);
    u64 h0 = splat2(s.xs[b0][k]);
    u64 h1 = splat2(s.xs[b0 + 1][k]);
    ACC6(rA, rB, aR, h0, h1)
    ACC6(zA, zB, aZ, h0, h1)
    ACC6(nA, nB, aI, h0, h1)
  }

  // recurrent contribution (K = 256): 16 chunks of 16, 4-deep pipeline
  if (t > 0) {
    for (int c = 0; c < 16; ++c) {
      __syncthreads();   // all readers of buffer (c+3)&3 (chunk c-1) done
      if (tid == 0 && c + 3 < 16) {
        int j = c + 3;
        mbar_expect(mb_w[j & 3], 12288u);
        bulk_g2s(smem_u32(&s.wbuf[j & 3][0][0]), wsrc + (size_t)j * 16 * 192,
                 12288u, mb_w[j & 3]);
      }
      mbar_wait(mb_w[c & 3], (c >> 2) & 1);
      const int buf = c & 3, kc = c * 16;
      #pragma unroll 16
      for (int kk = 0; kk < 16; ++kk) {
        const float* wr = &s.wbuf[buf][kk][0];
        ulonglong2 rA = *reinterpret_cast<const ulonglong2*>(wr + qa);
        ulonglong2 rB = *reinterpret_cast<const ulonglong2*>(wr + qb);
        ulonglong2 zA = *reinterpret_cast<const ulonglong2*>(wr + 64 + qa);
        ulonglong2 zB = *reinterpret_cast<const ulonglong2*>(wr + 64 + qb);
        ulonglong2 nA = *reinterpret_cast<const ulonglong2*>(wr + 128 + qa);
        ulonglong2 nB = *reinterpret_cast<const ulonglong2*>(wr + 128 + qb);
        u64 h0 = splat2(s.hs[b0][kc + kk]);
        u64 h1 = splat2(s.hs[b0 + 1][kc + kk]);
        ACC6(rA, rB, aR, h0, h1)
        ACC6(zA, zB, aZ, h0, h1)
        ACC6(nA, nB, aN, h0, h1)
      }
    }
  }

  // gates + masked update + write
  #pragma unroll
  for (int b = 0; b < 2; ++b) {
    float zz[8], nn[8];
    #pragma unroll
    for (int q = 0; q < 2; ++q) {
      #pragma unroll
      for (int p = 0; p < 2; ++p) {
        float2 r2 = unpk2(aR[b][q][p]);
        float2 z2 = unpk2(aZ[b][q][p]);
        float2 i2 = unpk2(aI[b][q][p]);
        float2 n2 = unpk2(aN[b][q][p]);
        #pragma unroll
        for (int e = 0; e < 2; ++e) {
          float xr = e ? r2.y : r2.x;
          float xz = e ? z2.y : z2.x;
          float xi = e ? i2.y : i2.x;
          float xn = e ? n2.y : n2.x;
          float r = __fdividef(1.f, 1.f + __expf(-xr));
          float z = __fdividef(1.f, 1.f + __expf(-xz));
          float n = tanhf(fmaf(r, xn, xi));
          int idx = q * 4 + p * 2 + e;
          zz[idx] = z; nn[idx] = n;
        }
      }
    }
    int row = bt * TB + b0 + b;
    bool act = t < s.ls[b0 + b];
    float oA[4], oB[4];
    #pragma unroll
    for (int i = 0; i < 4; ++i) {
      float holdA = (t > 0) ? s.hs[b0 + b][jt * 64 + qa + i] : 0.f;
      float holdB = (t > 0) ? s.hs[b0 + b][jt * 64 + qb + i] : 0.f;
      oA[i] = act ? fmaf(zz[i], holdA - nn[i], nn[i]) : holdA;
      oB[i] = act ? fmaf(zz[4 + i], holdB - nn[4 + i], nn[4 + i]) : holdB;
    }
    *reinterpret_cast<float4*>(&g_h[po][g][row][jt * 64 + qa]) =
        make_float4(oA[0], oA[1], oA[2], oA[3]);
    *reinterpret_cast<float4*>(&g_h[po][g][row][jt * 64 + qb]) =
        make_float4(oB[0], oB[1], oB[2], oB[3]);
  }
}

// ---------------- concat [state(:,0,:), action, h] ----------------
__global__ void k_concat(const float* __restrict__ state, const float* __restrict__ action) {
  int b = blockIdx.x, br = blockIdx.y;
  int p = g_invpos[b];
  int fp = g_finparp[p];
  for (int c = threadIdx.x; c < 272; c += blockDim.x) {
    float v;
    if (c < ND)       v = state[(size_t)b * NT * ND + c];
    else if (c == ND) v = action[b];
    else              v = g_h[fp][br][p][c - 16];
    g_xin[br][b][c] = v;
  }
}

// ---------------- FFMA2 tiled GEMM ----------------
template<bool RELU>
__global__ void __launch_bounds__(256)
k_gemm2(const float* __restrict__ A, const float* __restrict__ W,
        const float* __restrict__ bias, float* __restrict__ C,
        int K, int N)
{
  __shared__ float As[16][132];
  __shared__ float Ws[16][68];
  const int bm = blockIdx.x * 128;
  const int bn = blockIdx.y * 64;
  const int tid = threadIdx.x;
  const int mg = tid >> 4;
  const int ng = tid & 15;
  const int m0 = mg * 8;
  const int n0 = ng * 4;

  u64 acc[4][4];
  #pragma unroll
  for (int i = 0; i < 4; ++i)
    #pragma unroll
    for (int j = 0; j < 4; ++j) acc[i][j] = 0ull;

  for (int k0 = 0; k0 < K; k0 += 16) {
    #pragma unroll
    for (int e = 0; e < 2; ++e) {
      int idx = e * 256 + tid;
      int r = idx >> 2, c = idx & 3;
      float4 v = *reinterpret_cast<const float4*>(&A[(size_t)(bm + r) * K + k0 + c * 4]);
      As[c * 4 + 0][r] = v.x; As[c * 4 + 1][r] = v.y;
      As[c * 4 + 2][r] = v.z; As[c * 4 + 3][r] = v.w;
    }
    {
      int r = tid >> 2, c = tid & 3;
      float4 v = *reinterpret_cast<const float4*>(&W[(size_t)(bn + r) * K + k0 + c * 4]);
      Ws[c * 4 + 0][r] = v.x; Ws[c * 4 + 1][r] = v.y;
      Ws[c * 4 + 2][r] = v.z; Ws[c * 4 + 3][r] = v.w;
    }
    __syncthreads();
    #pragma unroll
    for (int k = 0; k < 16; ++k) {
      ulonglong2 a01 = *reinterpret_cast<const ulonglong2*>(&As[k][m0]);
      ulonglong2 a23 = *reinterpret_cast<const ulonglong2*>(&As[k][m0 + 4]);
      float4 wv = *reinterpret_cast<const float4*>(&Ws[k][n0]);
      u64 w2[4];
      w2[0] = splat2(wv.x); w2[1] = splat2(wv.y);
      w2[2] = splat2(wv.z); w2[3] = splat2(wv.w);
      #pragma unroll
      for (int n = 0; n < 4; ++n) {
        ffma2(acc[0][n], a01.x, w2[n]);
        ffma2(acc[1][n], a01.y, w2[n]);
        ffma2(acc[2][n], a23.x, w2[n]);
        ffma2(acc[3][n], a23.y, w2[n]);
      }
    }
    __syncthreads();
  }

  float bs[4];
  #pragma unroll
  for (int n = 0; n < 4; ++n) bs[n] = bias[bn + n0 + n];

  #pragma unroll
  for (int p = 0; p < 4; ++p) {
    float2 v0 = unpk2(acc[p][0]);
    float2 v1 = unpk2(acc[p][1]);
    float2 v2 = unpk2(acc[p][2]);
    float2 v3 = unpk2(acc[p][3]);
    int row = bm + m0 + p * 2;
    float4 lo = make_float4(v0.x + bs[0], v1.x + bs[1], v2.x + bs[2], v3.x + bs[3]);
    float4 hi = make_float4(v0.y + bs[0], v1.y + bs[1], v2.y + bs[2], v3.y + bs[3]);
    if (RELU) {
      lo.x = fmaxf(lo.x, 0.f); lo.y = fmaxf(lo.y, 0.f);
      lo.z = fmaxf(lo.z, 0.f); lo.w = fmaxf(lo.w, 0.f);
      hi.x = fmaxf(hi.x, 0.f); hi.y = fmaxf(hi.y, 0.f);
      hi.z = fmaxf(hi.z, 0.f); hi.w = fmaxf(hi.w, 0.f);
    }
    *reinterpret_cast<float4*>(&C[(size_t)row * N + bn + n0]) = lo;
    *reinterpret_cast<float4*>(&C[(size_t)(row + 1) * N + bn + n0]) = hi;
  }
}

// ---------------- q head ----------------
__global__ void k_q(const float* __restrict__ A, const float* __restrict__ qw,
                    const float* __restrict__ qb, float* __restrict__ out)
{
  __shared__ float red[64];
  int b = blockIdx.x;
  float sum = 0.f;
  for (int c = threadIdx.x; c < 256; c += 64) sum += A[(size_t)b * 256 + c] * qw[c];
  red[threadIdx.x] = sum;
  __syncthreads();
  if (threadIdx.x < 32) {
    float v = red[threadIdx.x] + red[threadIdx.x + 32];
    #pragma unroll
    for (int o = 16; o; o >>= 1) v += __shfl_down_sync(0xffffffffu, v, o);
    if (threadIdx.x == 0) out[b] = v + qb[0];
  }
}

// ---------------- launch ----------------
extern "C" void kernel_launch(void* const* d_in, const int* in_sizes, int n_in,
                              void* d_out, int out_size)
{
  const float* state   = (const float*)d_in[0];
  const float* action  = (const float*)d_in[1];
  const int*   lengths = (const int*)d_in[2];

  const float* gWih[2]; const float* gWhh[2];
  const float* gbih[2]; const float* gbhh[2];
  const float* fcw[2][5]; const float* fcb[2][5];
  for (int br = 0; br < 2; ++br) {
    int base = 3 + br * 14;
    gWih[br] = (const float*)d_in[base + 0];
    gWhh[br] = (const float*)d_in[base + 1];
    gbih[br] = (const float*)d_in[base + 2];
    gbhh[br] = (const float*)d_in[base + 3];
    for (int l = 0; l < 5; ++l) {
      fcw[br][l] = (const float*)d_in[base + 4 + 2 * l];
      fcb[br][l] = (const float*)d_in[base + 5 + 2 * l];
    }
  }

  float *p_xin, *p_a1, *p_a2, *p_a3, *p_a4;
  cudaGetSymbolAddress((void**)&p_xin, g_xin);
  cudaGetSymbolAddress((void**)&p_a1, g_a1);
  cudaGetSymbolAddress((void**)&p_a2, g_a2);
  cudaGetSymbolAddress((void**)&p_a3, g_a3);
  cudaGetSymbolAddress((void**)&p_a4, g_a4);

  cudaFuncSetAttribute(k_gru_step, cudaFuncAttributeMaxDynamicSharedMemorySize,
                       (int)sizeof(GruS));

  // prep (2 launches, so ncu -s 5 lands on k_gru_step t=3)
  k_sort<<<1, 1024>>>(lengths);
  k_prep<<<(WHH_N + 8 * 3136 + 255) / 256, 256>>>(gWhh[0], gWhh[1],
                                                  gWih[0], gbih[0], gbhh[0],
                                                  gWih[1], gbih[1], gbhh[1]);

  // recurrent steps
  for (int t = 0; t < NT; ++t) {
    k_gru_step<<<dim3(NBT, 4, 2), THR, sizeof(GruS)>>>(state, t);
  }

  k_concat<<<dim3(NB, 2), 128>>>(state, action);

  float* outp = (float*)d_out;
  for (int br = 0; br < 2; ++br) {
    float* xin = p_xin + (size_t)br * NB * 272;
    float* a1  = p_a1  + (size_t)br * NB * 1024;
    float* a2  = p_a2  + (size_t)br * NB * 1024;
    float* a3  = p_a3  + (size_t)br * NB * 512;
    float* a4  = p_a4  + (size_t)br * NB * 256;
    k_gemm2<true><<<dim3(16, 16), 256>>>(xin, fcw[br][0], fcb[br][0], a1, 272, 1024);
    k_gemm2<true><<<dim3(16, 16), 256>>>(a1,  fcw[br][1], fcb[br][1], a2, 1024, 1024);
    k_gemm2<true><<<dim3(16,  8), 256>>>(a2,  fcw[br][2], fcb[br][2], a3, 1024, 512);
    k_gemm2<true><<<dim3(16,  4), 256>>>(a3,  fcw[br][3], fcb[br][3], a4, 512, 256);
    k_q<<<NB, 64>>>(a4, fcw[br][4], fcb[br][4], outp + (size_t)br * NB);
  }
}

// round 6
// speedup vs baseline: 1.0397x; 1.0397x over previous
#include <cuda_runtime.h>
#include <math.h>

#define NB 2048
#define NT 64
#define ND 15
#define NH 256
#define TB 64        // batch rows per GRU CTA (sorted tile)
#define NBT 32       // NB / TB
#define THR 128
#define WHH_N (2 * 4 * 256 * 192)

typedef unsigned long long u64;

// ---------------- f32x2 packed-FMA helpers ----------------
__device__ __forceinline__ void ffma2(u64& d, u64 a, u64 b) {
  asm("fma.rn.f32x2 %0, %1, %2, %3;" : "=l"(d) : "l"(a), "l"(b), "l"(d));
}
__device__ __forceinline__ u64 splat2(float w) {
  u64 d; asm("mov.b64 %0, {%1, %1};" : "=l"(d) : "f"(w)); return d;
}
__device__ __forceinline__ float2 unpk2(u64 v) {
  float2 r; asm("mov.b64 {%0, %1}, %2;" : "=f"(r.x), "=f"(r.y) : "l"(v)); return r;
}

// ---------------- mbarrier / bulk-copy helpers ----------------
__device__ __forceinline__ unsigned smem_u32(const void* p) {
  unsigned a;
  asm("{ .reg .u64 t; cvta.to.shared.u64 t, %1; cvt.u32.u64 %0, t; }" : "=r"(a) : "l"(p));
  return a;
}
__device__ __forceinline__ void mbar_init(unsigned mbar, unsigned cnt) {
  asm volatile("mbarrier.init.shared.b64 [%0], %1;" :: "r"(mbar), "r"(cnt) : "memory");
}
__device__ __forceinline__ void mbar_expect(unsigned mbar, unsigned bytes) {
  asm volatile("mbarrier.arrive.expect_tx.shared.b64 _, [%0], %1;"
               :: "r"(mbar), "r"(bytes) : "memory");
}
__device__ __forceinline__ void bulk_g2s(unsigned dst, const void* src,
                                         unsigned bytes, unsigned mbar) {
  asm volatile(
      "cp.async.bulk.shared::cta.global.mbarrier::complete_tx::bytes [%0], [%1], %2, [%3];"
      :: "r"(dst), "l"(src), "r"(bytes), "r"(mbar) : "memory");
}
__device__ __forceinline__ void mbar_wait(unsigned mbar, unsigned parity) {
  asm volatile(
      "{\n\t.reg .pred P;\n\t"
      "W%=:\n\t"
      "mbarrier.try_wait.parity.acquire.cta.shared::cta.b64 P, [%0], %1, 0x989680;\n\t"
      "@P bra.uni D%=;\n\t"
      "bra.uni W%=;\n\t"
      "D%=:\n\t}"
      :: "r"(mbar), "r"(parity) : "memory");
}

// ---------------- device scratch ----------------
__device__ float g_h[2][2][NB][NH];          // [parity][gru][sorted_pos][h]
__device__ float g_whhB[WHH_N];              // [g][jt][k][gate*64+c]
__device__ float g_wblk[8][3136];            // [g*4+jt]{ wihT[15][192], cbA[192], cbHn[64] }
__device__ float g_xin[2][NB][272];
__device__ float g_a1[2][NB][1024];
__device__ float g_a2[2][NB][1024];
__device__ float g_a3[2][NB][512];
__device__ float g_a4[2][NB][256];
__device__ int   g_perm[NB];
__device__ int   g_off[66];
__device__ int   g_hist[66];
__device__ int   g_tilemax[NBT];
__device__ int   g_invpos[NB];
__device__ int   g_finparp[NB];
__device__ int   g_lsort[NB];

// ---------------- fused length sort (single block) ----------------
__global__ void k_sort(const int* __restrict__ lengths) {
  int tid = threadIdx.x;
  if (tid < 66) g_hist[tid] = 0;
  __syncthreads();
  for (int b = tid; b < NB; b += 1024) atomicAdd(&g_hist[lengths[b]], 1);
  __syncthreads();
  if (tid == 0) {
    int s = 0;
    for (int l = 0; l < 66; ++l) { g_off[l] = s; s += g_hist[l]; }
  }
  __syncthreads();
  for (int b = tid; b < NB; b += 1024) {
    int p = atomicAdd(&g_off[lengths[b]], 1);
    g_perm[p] = b;
  }
  __syncthreads();
  if (tid < NBT) g_tilemax[tid] = lengths[g_perm[tid * TB + TB - 1]];
  __syncthreads();
  for (int p = tid; p < NB; p += 1024) {
    int b = g_perm[p];
    g_invpos[b] = p;
    g_finparp[p] = g_tilemax[p >> 6] & 1;
    g_lsort[p] = lengths[b];
  }
}

// ---------------- fused weight prep ----------------
__global__ void k_prep(const float* __restrict__ Whh0, const float* __restrict__ Whh1,
                       const float* __restrict__ Wih0, const float* __restrict__ bih0,
                       const float* __restrict__ bhh0,
                       const float* __restrict__ Wih1, const float* __restrict__ bih1,
                       const float* __restrict__ bhh1) {
  int i = blockIdx.x * blockDim.x + threadIdx.x;
  if (i < WHH_N) {
    int c  = i % 192;
    int k  = (i / 192) % 256;
    int jt = (i / (192 * 256)) & 3;
    int g  = i / (192 * 256 * 4);
    const float* W = g ? Whh1 : Whh0;
    int gg = c >> 6, cc = c & 63;
    g_whhB[i] = W[(size_t)(gg * 256 + jt * 64 + cc) * 256 + k];
    return;
  }
  int j = i - WHH_N;
  if (j >= 8 * 3136) return;
  int o  = j % 3136;
  int jt = (j / 3136) & 3;
  int g  = j / (3136 * 4);
  const float* Wih = g ? Wih1 : Wih0;
  const float* bih = g ? bih1 : bih0;
  const float* bhh = g ? bhh1 : bhh0;
  float v;
  if (o < 2880) {
    int k = o / 192, c = o % 192;
    int gg = c >> 6, cc = c & 63;
    v = Wih[(size_t)(gg * 256 + jt * 64 + cc) * ND + k];
  } else if (o < 3072) {
    int c = o - 2880;
    int gg = c >> 6, cc = c & 63;
    int row = gg * 256 + jt * 64 + cc;
    v = (gg < 2) ? (bih[row] + bhh[row]) : bih[row];
  } else {
    v = bhh[512 + jt * 64 + (o - 3072)];
  }
  g_wblk[g * 4 + jt][o] = v;
}

// ---------------- GRU step kernel (LDG-direct weights, 8b x 4c per thread) ----------------
struct GruS {
  float hs[TB][256];   // 65536 B (one bulk copy)
  float xs[TB][ND];    //  3840 B
  int   ls[TB];
  u64   mb[2];
};

__global__ void __launch_bounds__(THR)
k_gru_step(const float* __restrict__ state, int t)
{
  extern __shared__ char sraw[];
  GruS& s = *reinterpret_cast<GruS*>(sraw);
  const int bt = blockIdx.x, jt = blockIdx.y, g = blockIdx.z;
  const int tid = threadIdx.x;
  const int pi = t & 1, po = pi ^ 1;

  if (t >= g_tilemax[bt]) return;   // frozen tile

  const unsigned mb_h = smem_u32(&s.mb[0]);
  const int gjt = g * 4 + jt;
  const float* __restrict__ wp = g_whhB + (size_t)gjt * 256 * 192;
  const float* __restrict__ wi = &g_wblk[gjt][0];

  if (tid == 0) mbar_init(mb_h, 1);
  __syncthreads();
  if (tid == 0 && t > 0) {
    mbar_expect(mb_h, 65536u);
    bulk_g2s(smem_u32(&s.hs[0][0]), &g_h[pi][g][bt * TB][0], 65536u, mb_h);
  }

  // x gather + lengths (overlaps h TMA flight)
  for (int i = tid; i < TB * ND; i += THR) {
    int b = i / ND, c = i % ND;
    s.xs[b][c] = state[((size_t)g_perm[bt * TB + b] * NT + t) * ND + c];
  }
  if (tid < TB) s.ls[tid] = g_lsort[bt * TB + tid];
  __syncthreads();

  const int cg = tid & 15;   // 16 col groups x 4 cols
  const int bg = tid >> 4;   // 8 batch groups x 8 rows
  const int b0 = bg * 8;
  const int c4 = cg * 4;

  // accumulators: [batch row][col pair] packed f32x2
  u64 aR[8][2], aZ[8][2], aI[8][2], aN[8][2];
  {
    ulonglong2 bR = *reinterpret_cast<const ulonglong2*>(wi + 2880 + c4);
    ulonglong2 bZ = *reinterpret_cast<const ulonglong2*>(wi + 2944 + c4);
    ulonglong2 bI = *reinterpret_cast<const ulonglong2*>(wi + 3008 + c4);
    ulonglong2 bN = *reinterpret_cast<const ulonglong2*>(wi + 3072 + c4);
    #pragma unroll
    for (int i = 0; i < 8; ++i) {
      aR[i][0] = bR.x; aR[i][1] = bR.y;
      aZ[i][0] = bZ.x; aZ[i][1] = bZ.y;
      aI[i][0] = bI.x; aI[i][1] = bI.y;
      aN[i][0] = bN.x; aN[i][1] = bN.y;
    }
  }

  // input-gate contribution (K = 15), weights LDG-direct from blocked layout
  #pragma unroll
  for (int k = 0; k < ND; ++k) {
    const float* row = wi + k * 192;
    ulonglong2 wr = *reinterpret_cast<const ulonglong2*>(row + c4);
    ulonglong2 wz = *reinterpret_cast<const ulonglong2*>(row + 64 + c4);
    ulonglong2 wn = *reinterpret_cast<const ulonglong2*>(row + 128 + c4);
    #pragma unroll
    for (int i = 0; i < 8; ++i) {
      u64 xv = splat2(s.xs[b0 + i][k]);
      ffma2(aR[i][0], xv, wr.x); ffma2(aR[i][1], xv, wr.y);
      ffma2(aZ[i][0], xv, wz.x); ffma2(aZ[i][1], xv, wz.y);
      ffma2(aI[i][0], xv, wn.x); ffma2(aI[i][1], xv, wn.y);
    }
  }

  // recurrent contribution (K = 256): weights streamed LDG->regs, distance-2 pipeline
  if (t > 0) {
    mbar_wait(mb_h, 0);
    ulonglong2 fr[2], fz[2], fn[2];
    #pragma unroll
    for (int p = 0; p < 2; ++p) {
      const float* row = wp + p * 192;
      fr[p] = *reinterpret_cast<const ulonglong2*>(row + c4);
      fz[p] = *reinterpret_cast<const ulonglong2*>(row + 64 + c4);
      fn[p] = *reinterpret_cast<const ulonglong2*>(row + 128 + c4);
    }
    #pragma unroll 4
    for (int kk = 0; kk < 256; ++kk) {
      const int p = kk & 1;
      ulonglong2 wr = fr[p], wz = fz[p], wn = fn[p];
      int kp = (kk + 2 < 256) ? kk + 2 : 255;
      const float* row = wp + kp * 192;
      fr[p] = *reinterpret_cast<const ulonglong2*>(row + c4);
      fz[p] = *reinterpret_cast<const ulonglong2*>(row + 64 + c4);
      fn[p] = *reinterpret_cast<const ulonglong2*>(row + 128 + c4);
      #pragma unroll
      for (int i = 0; i < 8; ++i) {
        u64 hv = splat2(s.hs[b0 + i][kk]);   // broadcast scalar LDS (cheap)
        ffma2(aR[i][0], hv, wr.x); ffma2(aR[i][1], hv, wr.y);
        ffma2(aZ[i][0], hv, wz.x); ffma2(aZ[i][1], hv, wz.y);
        ffma2(aN[i][0], hv, wn.x); ffma2(aN[i][1], hv, wn.y);
      }
    }
  }

  // gates + masked update + write
  #pragma unroll
  for (int i = 0; i < 8; ++i) {
    bool act = (t < s.ls[b0 + i]);
    float2 r0 = unpk2(aR[i][0]), r1 = unpk2(aR[i][1]);
    float2 z0 = unpk2(aZ[i][0]), z1 = unpk2(aZ[i][1]);
    float2 i0 = unpk2(aI[i][0]), i1 = unpk2(aI[i][1]);
    float2 n0 = unpk2(aN[i][0]), n1 = unpk2(aN[i][1]);
    float xr[4] = {r0.x, r0.y, r1.x, r1.y};
    float xz[4] = {z0.x, z0.y, z1.x, z1.y};
    float xi[4] = {i0.x, i0.y, i1.x, i1.y};
    float xn[4] = {n0.x, n0.y, n1.x, n1.y};
    float o[4];
    #pragma unroll
    for (int e = 0; e < 4; ++e) {
      float r = __fdividef(1.f, 1.f + __expf(-xr[e]));
      float z = __fdividef(1.f, 1.f + __expf(-xz[e]));
      float n = tanhf(fmaf(r, xn[e], xi[e]));
      float hold = (t > 0) ? s.hs[b0 + i][jt * 64 + c4 + e] : 0.f;
      o[e] = act ? fmaf(z, hold - n, n) : hold;
    }
    *reinterpret_cast<float4*>(&g_h[po][g][bt * TB + b0 + i][jt * 64 + c4]) =
        make_float4(o[0], o[1], o[2], o[3]);
  }
}

// ---------------- concat [state(:,0,:), action, h] ----------------
__global__ void k_concat(const float* __restrict__ state, const float* __restrict__ action) {
  int b = blockIdx.x, br = blockIdx.y;
  int p = g_invpos[b];
  int fp = g_finparp[p];
  for (int c = threadIdx.x; c < 272; c += blockDim.x) {
    float v;
    if (c < ND)       v = state[(size_t)b * NT * ND + c];
    else if (c == ND) v = action[b];
    else              v = g_h[fp][br][p][c - 16];
    g_xin[br][b][c] = v;
  }
}

// ---------------- FFMA2 tiled GEMM ----------------
template<bool RELU>
__global__ void __launch_bounds__(256)
k_gemm2(const float* __restrict__ A, const float* __restrict__ W,
        const float* __restrict__ bias, float* __restrict__ C,
        int K, int N)
{
  __shared__ float As[16][132];
  __shared__ float Ws[16][68];
  const int bm = blockIdx.x * 128;
  const int bn = blockIdx.y * 64;
  const int tid = threadIdx.x;
  const int mg = tid >> 4;
  const int ng = tid & 15;
  const int m0 = mg * 8;
  const int n0 = ng * 4;

  u64 acc[4][4];
  #pragma unroll
  for (int i = 0; i < 4; ++i)
    #pragma unroll
    for (int j = 0; j < 4; ++j) acc[i][j] = 0ull;

  for (int k0 = 0; k0 < K; k0 += 16) {
    #pragma unroll
    for (int e = 0; e < 2; ++e) {
      int idx = e * 256 + tid;
      int r = idx >> 2, c = idx & 3;
      float4 v = *reinterpret_cast<const float4*>(&A[(size_t)(bm + r) * K + k0 + c * 4]);
      As[c * 4 + 0][r] = v.x; As[c * 4 + 1][r] = v.y;
      As[c * 4 + 2][r] = v.z; As[c * 4 + 3][r] = v.w;
    }
    {
      int r = tid >> 2, c = tid & 3;
      float4 v = *reinterpret_cast<const float4*>(&W[(size_t)(bn + r) * K + k0 + c * 4]);
      Ws[c * 4 + 0][r] = v.x; Ws[c * 4 + 1][r] = v.y;
      Ws[c * 4 + 2][r] = v.z; Ws[c * 4 + 3][r] = v.w;
    }
    __syncthreads();
    #pragma unroll
    for (int k = 0; k < 16; ++k) {
      ulonglong2 a01 = *reinterpret_cast<const ulonglong2*>(&As[k][m0]);
      ulonglong2 a23 = *reinterpret_cast<const ulonglong2*>(&As[k][m0 + 4]);
      float4 wv = *reinterpret_cast<const float4*>(&Ws[k][n0]);
      u64 w2[4];
      w2[0] = splat2(wv.x); w2[1] = splat2(wv.y);
      w2[2] = splat2(wv.z); w2[3] = splat2(wv.w);
      #pragma unroll
      for (int n = 0; n < 4; ++n) {
        ffma2(acc[0][n], a01.x, w2[n]);
        ffma2(acc[1][n], a01.y, w2[n]);
        ffma2(acc[2][n], a23.x, w2[n]);
        ffma2(acc[3][n], a23.y, w2[n]);
      }
    }
    __syncthreads();
  }

  float bs[4];
  #pragma unroll
  for (int n = 0; n < 4; ++n) bs[n] = bias[bn + n0 + n];

  #pragma unroll
  for (int p = 0; p < 4; ++p) {
    float2 v0 = unpk2(acc[p][0]);
    float2 v1 = unpk2(acc[p][1]);
    float2 v2 = unpk2(acc[p][2]);
    float2 v3 = unpk2(acc[p][3]);
    int row = bm + m0 + p * 2;
    float4 lo = make_float4(v0.x + bs[0], v1.x + bs[1], v2.x + bs[2], v3.x + bs[3]);
    float4 hi = make_float4(v0.y + bs[0], v1.y + bs[1], v2.y + bs[2], v3.y + bs[3]);
    if (RELU) {
      lo.x = fmaxf(lo.x, 0.f); lo.y = fmaxf(lo.y, 0.f);
      lo.z = fmaxf(lo.z, 0.f); lo.w = fmaxf(lo.w, 0.f);
      hi.x = fmaxf(hi.x, 0.f); hi.y = fmaxf(hi.y, 0.f);
      hi.z = fmaxf(hi.z, 0.f); hi.w = fmaxf(hi.w, 0.f);
    }
    *reinterpret_cast<float4*>(&C[(size_t)row * N + bn + n0]) = lo;
    *reinterpret_cast<float4*>(&C[(size_t)(row + 1) * N + bn + n0]) = hi;
  }
}

// ---------------- q head ----------------
__global__ void k_q(const float* __restrict__ A, const float* __restrict__ qw,
                    const float* __restrict__ qb, float* __restrict__ out)
{
  __shared__ float red[64];
  int b = blockIdx.x;
  float sum = 0.f;
  for (int c = threadIdx.x; c < 256; c += 64) sum += A[(size_t)b * 256 + c] * qw[c];
  red[threadIdx.x] = sum;
  __syncthreads();
  if (threadIdx.x < 32) {
    float v = red[threadIdx.x] + red[threadIdx.x + 32];
    #pragma unroll
    for (int o = 16; o; o >>= 1) v += __shfl_down_sync(0xffffffffu, v, o);
    if (threadIdx.x == 0) out[b] = v + qb[0];
  }
}

// ---------------- launch ----------------
extern "C" void kernel_launch(void* const* d_in, const int* in_sizes, int n_in,
                              void* d_out, int out_size)
{
  const float* state   = (const float*)d_in[0];
  const float* action  = (const float*)d_in[1];
  const int*   lengths = (const int*)d_in[2];

  const float* gWih[2]; const float* gWhh[2];
  const float* gbih[2]; const float* gbhh[2];
  const float* fcw[2][5]; const float* fcb[2][5];
  for (int br = 0; br < 2; ++br) {
    int base = 3 + br * 14;
    gWih[br] = (const float*)d_in[base + 0];
    gWhh[br] = (const float*)d_in[base + 1];
    gbih[br] = (const float*)d_in[base + 2];
    gbhh[br] = (const float*)d_in[base + 3];
    for (int l = 0; l < 5; ++l) {
      fcw[br][l] = (const float*)d_in[base + 4 + 2 * l];
      fcb[br][l] = (const float*)d_in[base + 5 + 2 * l];
    }
  }

  float *p_xin, *p_a1, *p_a2, *p_a3, *p_a4;
  cudaGetSymbolAddress((void**)&p_xin, g_xin);
  cudaGetSymbolAddress((void**)&p_a1, g_a1);
  cudaGetSymbolAddress((void**)&p_a2, g_a2);
  cudaGetSymbolAddress((void**)&p_a3, g_a3);
  cudaGetSymbolAddress((void**)&p_a4, g_a4);

  cudaFuncSetAttribute(k_gru_step, cudaFuncAttributeMaxDynamicSharedMemorySize,
                       (int)sizeof(GruS));

  // prep
  k_sort<<<1, 1024>>>(lengths);
  k_prep<<<(WHH_N + 8 * 3136 + 255) / 256, 256>>>(gWhh[0], gWhh[1],
                                                  gWih[0], gbih[0], gbhh[0],
                                                  gWih[1], gbih[1], gbhh[1]);

  // recurrent steps
  for (int t = 0; t < NT; ++t) {
    k_gru_step<<<dim3(NBT, 4, 2), THR, sizeof(GruS)>>>(state, t);
  }

  k_concat<<<dim3(NB, 2), 128>>>(state, action);

  float* outp = (float*)d_out;
  for (int br = 0; br < 2; ++br) {
    float* xin = p_xin + (size_t)br * NB * 272;
    float* a1  = p_a1  + (size_t)br * NB * 1024;
    float* a2  = p_a2  + (size_t)br * NB * 1024;
    float* a3  = p_a3  + (size_t)br * NB * 512;
    float* a4  = p_a4  + (size_t)br * NB * 256;
    k_gemm2<true><<<dim3(16, 16), 256>>>(xin, fcw[br][0], fcb[br][0], a1, 272, 1024);
    k_gemm2<true><<<dim3(16, 16), 256>>>(a1,  fcw[br][1], fcb[br][1], a2, 1024, 1024);
    k_gemm2<true><<<dim3(16,  8), 256>>>(a2,  fcw[br][2], fcb[br][2], a3, 1024, 512);
    k_gemm2<true><<<dim3(16,  4), 256>>>(a3,  fcw[br][3], fcb[br][3], a4, 512, 256);
    k_q<<<NB, 64>>>(a4, fcw[br][4], fcb[br][4], outp + (size_t)br * NB);
  }
}